// round 7
// baseline (speedup 1.0000x reference)
#include <cuda_runtime.h>
#include <cuda_bf16.h>

// AttentionSE3: segment-softmax graph attention, edges sorted by dst.
// R3: (1) offsets precomputed by an edge-parallel boundary kernel (no per-warp
// binary search), (2) pair-processed inner loop with double-buffered prefetch
// (MLP=4/warp, softmax rescale chain halved), (3) __ldcs streaming loads for
// the 656MB key/value stream, q pre-scaled by 1/sqrt(128).
//
// One warp per destination node. Lane l owns fiber elements [4l,4l+4) of the
// 128-wide flattened (C=32, DV=4) layout; head h = l/4 reduces its 16-elem
// dot across the 4-lane group via two shfl_xor, and that same group is the
// set of lanes whose value float4 needs w[h]. No smem, no atomics.

#define FULLMASK 0xFFFFFFFFu

__device__ int g_off[65537];   // off[n] = first edge with dst >= n; off[N] = E

__global__ __launch_bounds__(256) void offsets_kernel(
    const int* __restrict__ dst, int N, int E)
{
    int e = blockIdx.x * blockDim.x + threadIdx.x;
    if (e >= E) return;
    int d = __ldg(dst + e);
    int prev = (e > 0) ? __ldg(dst + e - 1) : -1;
    for (int n = prev + 1; n <= d; ++n) g_off[n] = e;   // each off[n] written once
    if (e == E - 1) {
        for (int n = d + 1; n <= N; ++n) g_off[n] = E;
    }
}

__global__ __launch_bounds__(256) void se3_attn_kernel(
    const float* __restrict__ key,     // (E, 8, 16) = (E,128)
    const float* __restrict__ q0,      // (N, 32, 1)
    const float* __restrict__ q1,      // (N, 32, 3)
    const float* __restrict__ value,   // (E, 32, 4)
    float*       __restrict__ out,     // [N*32] ++ [N*32*3]
    int N)
{
    const int n = (int)((blockIdx.x * blockDim.x + threadIdx.x) >> 5);
    const int lane = threadIdx.x & 31;
    if (n >= N) return;

    const float scale = 0.08838834764831845f; // 1/sqrt(128)

    // Per-lane query fragment (c = lane, d4 = 0..3), pre-scaled.
    float4 q;
    q.x = __ldg(q0 + (size_t)n * 32 + lane) * scale;
    const float* q1p = q1 + ((size_t)n * 32 + lane) * 3;
    q.y = __ldg(q1p + 0) * scale;
    q.z = __ldg(q1p + 1) * scale;
    q.w = __ldg(q1p + 2) * scale;

    const int e0 = g_off[n];
    const int e1 = g_off[n + 1];
    int rem = e1 - e0;

    float  m   = -1e30f;
    float  den = 0.0f;
    float4 acc = make_float4(0.f, 0.f, 0.f, 0.f);

    const float4* kp = (const float4*)key   + (size_t)e0 * 32 + lane;
    const float4* vp = (const float4*)value + (size_t)e0 * 32 + lane;

    // Pair-processed mainloop, double-buffered: while computing pair A,
    // pair B's 4 loads (2x key, 2x value float4) are in flight.
    float4 ka0, ka1, va0, va1;
    if (rem >= 2) {
        ka0 = __ldcs(kp);      ka1 = __ldcs(kp + 32);
        va0 = __ldcs(vp);      va1 = __ldcs(vp + 32);
        kp += 64; vp += 64;
    }
    while (rem >= 2) {
        float4 kb0, kb1, vb0, vb1;
        const bool more = (rem >= 4);
        if (more) {
            kb0 = __ldcs(kp);  kb1 = __ldcs(kp + 32);
            vb0 = __ldcs(vp);  vb1 = __ldcs(vp + 32);
            kp += 64; vp += 64;
        }
        // two independent head dots -> ILP through the shfl chain
        float d0 = ka0.x * q.x + ka0.y * q.y + ka0.z * q.z + ka0.w * q.w;
        float d1 = ka1.x * q.x + ka1.y * q.y + ka1.z * q.z + ka1.w * q.w;
        d0 += __shfl_xor_sync(FULLMASK, d0, 1);
        d1 += __shfl_xor_sync(FULLMASK, d1, 1);
        d0 += __shfl_xor_sync(FULLMASK, d0, 2);
        d1 += __shfl_xor_sync(FULLMASK, d1, 2);

        float nm = fmaxf(m, fmaxf(d0, d1));
        float sc = __expf(m - nm);        // first iter: exp(-huge) -> 0
        float p0 = __expf(d0 - nm);
        float p1 = __expf(d1 - nm);
        m = nm;
        den   = fmaf(den,   sc, p0 + p1);
        acc.x = fmaf(acc.x, sc, fmaf(p0, va0.x, p1 * va1.x));
        acc.y = fmaf(acc.y, sc, fmaf(p0, va0.y, p1 * va1.y));
        acc.z = fmaf(acc.z, sc, fmaf(p0, va0.z, p1 * va1.z));
        acc.w = fmaf(acc.w, sc, fmaf(p0, va0.w, p1 * va1.w));

        ka0 = kb0; ka1 = kb1; va0 = vb0; va1 = vb1;
        rem -= 2;
    }
    if (rem == 1) {   // odd tail: recompute pointer from e1-1 (path-independent)
        const float4* kq = (const float4*)key   + (size_t)(e1 - 1) * 32 + lane;
        const float4* vq = (const float4*)value + (size_t)(e1 - 1) * 32 + lane;
        float4 kc = __ldcs(kq);
        float4 vc = __ldcs(vq);
        float d0 = kc.x * q.x + kc.y * q.y + kc.z * q.z + kc.w * q.w;
        d0 += __shfl_xor_sync(FULLMASK, d0, 1);
        d0 += __shfl_xor_sync(FULLMASK, d0, 2);
        float nm = fmaxf(m, d0);
        float sc = __expf(m - nm);
        float p  = __expf(d0 - nm);
        m = nm;
        den   = fmaf(den,   sc, p);
        acc.x = fmaf(acc.x, sc, p * vc.x);
        acc.y = fmaf(acc.y, sc, p * vc.y);
        acc.z = fmaf(acc.z, sc, p * vc.z);
        acc.w = fmaf(acc.w, sc, p * vc.w);
    }

    const float inv = (den > 0.0f) ? (1.0f / den) : 0.0f;

    // out0: (N,32,1) then out1: (N,32,3), concatenated flat
    out[(size_t)n * 32 + lane] = acc.x * inv;
    float* o1 = out + (size_t)N * 32 + ((size_t)n * 32 + lane) * 3;
    o1[0] = acc.y * inv;
    o1[1] = acc.z * inv;
    o1[2] = acc.w * inv;
}

extern "C" void kernel_launch(void* const* d_in, const int* in_sizes, int n_in,
                              void* d_out, int out_size) {
    const float* key   = (const float*)d_in[0];
    const float* q0    = (const float*)d_in[1];
    const float* q1    = (const float*)d_in[2];
    const float* value = (const float*)d_in[3];
    const int*   dst   = (const int*)d_in[4];
    float* out = (float*)d_out;

    const int E = in_sizes[0] / 128;   // key is (E, 8, 16)
    const int N = in_sizes[1] / 32;    // query_0 is (N, 32, 1)

    offsets_kernel<<<(E + 255) / 256, 256>>>(dst, N, E);

    const int threads = 256;                 // 8 warps = 8 nodes per block
    const int blocks  = (N + 7) / 8;
    se3_attn_kernel<<<blocks, threads>>>(key, q0, q1, value, out, N);
}